// round 13
// baseline (speedup 1.0000x reference)
#include <cuda_runtime.h>
#include <cuda_bf16.h>
#include <math.h>

#define BB   8192
#define EE   4
#define KK   16
#define DD   128
#define AGG_COLS 512          // E*D
#define PREP_BLKS 161         // 32 M-tiles + 1 c + 128 V
#define GATHER_BLKS (BB * EE / 8)   // 4096
#define NTILES (BB / 64)      // 128

// ---------------- scratch (static device globals; no allocation) -------------
__device__ __align__(256) __nv_bfloat16 g_aggh[(size_t)BB * AGG_COLS]; // [B,512] bf16 means
__device__ __align__(256) __nv_bfloat16 g_Vh[(size_t)BB * DD];         // bf16 emb_end*sigmoid(path)
__device__ __align__(256) __nv_bfloat16 g_Mh[(size_t)AGG_COLS * DD];   // [512,128] bf16
__device__ __align__(256) float         g_c[DD];                       // folded bias

// dependency flags (reset each call by k_reset)
__device__ int g_flag_M;              // target 33 (32 M blocks + c)
__device__ int g_flag_V[NTILES];      // target 1  (V block v <-> tile v)
__device__ int g_flag_T[NTILES];      // target 32 (32 gather blocks per tile)

__device__ __forceinline__ unsigned s2u(const void* p) {
    return (unsigned)__cvta_generic_to_shared(p);
}
__device__ __forceinline__ void cpasync16(unsigned saddr, const void* gptr) {
    asm volatile("cp.async.cg.shared.global [%0], [%1], 16;" :: "r"(saddr), "l"(gptr));
}
__device__ __forceinline__ void spin_until(int* p, int target) {
    while (atomicAdd(p, 0) < target) __nanosleep(64);
}

// ---------------------------------------------------------------------------
__global__ void k_reset() {
    int t = threadIdx.x;
    if (t < NTILES) { g_flag_V[t] = 0; g_flag_T[t] = 0; }
    if (t == 0) g_flag_M = 0;
}

// ---------------------------------------------------------------------------
// k_main: prep blocks (hidden under the gather stream) + gather, with flag signals.
__global__ __launch_bounds__(256) void k_main(const int*   __restrict__ nbidx,
                                              const float* __restrict__ emb_start,
                                              const float* __restrict__ W1,
                                              const float* __restrict__ W2,
                                              const float* __restrict__ b1,
                                              const float* __restrict__ b2,
                                              const int*   __restrict__ end_node,
                                              const int*   __restrict__ path,
                                              const float* __restrict__ emb_end,
                                              const float* __restrict__ emb_path) {
    int bid = blockIdx.x;
    int tid = threadIdx.x;
#if __CUDA_ARCH__ >= 900
    if (tid == 0) cudaTriggerProgrammaticLaunchCompletion();
#endif

    if (bid >= PREP_BLKS) {
        // ---------------- gather (hot path) ----------------
        int gblk = bid - PREP_BLKS;                      // 0..4095
        int w    = gblk * 8 + (tid >> 5);                // 0..32767 (b,e) pair
        int lane = tid & 31;

        const int4* ip = (const int4*)(nbidx + (size_t)w * KK);
        int4 id0 = __ldg(ip + 0);
        int4 id1 = __ldg(ip + 1);
        int4 id2 = __ldg(ip + 2);
        int4 id3 = __ldg(ip + 3);

        const float* base = emb_start + lane * 4;
        float4 acc = make_float4(0.f, 0.f, 0.f, 0.f);
#define ACCUM(idx) { const float4 v = *(const float4*)(base + (size_t)(idx) * DD); \
                     acc.x += v.x; acc.y += v.y; acc.z += v.z; acc.w += v.w; }
        ACCUM(id0.x) ACCUM(id0.y) ACCUM(id0.z) ACCUM(id0.w)
        ACCUM(id1.x) ACCUM(id1.y) ACCUM(id1.z) ACCUM(id1.w)
        ACCUM(id2.x) ACCUM(id2.y) ACCUM(id2.z) ACCUM(id2.w)
        ACCUM(id3.x) ACCUM(id3.y) ACCUM(id3.z) ACCUM(id3.w)
#undef ACCUM
        const float inv = 1.f / (float)KK;
        __nv_bfloat162 h0 = __floats2bfloat162_rn(acc.x * inv, acc.y * inv);
        __nv_bfloat162 h1 = __floats2bfloat162_rn(acc.z * inv, acc.w * inv);
        uint2 pk; pk.x = *(unsigned*)&h0; pk.y = *(unsigned*)&h1;
        *(uint2*)(g_aggh + (size_t)w * DD + lane * 4) = pk;  // w*128 == b*512+e*128
        __syncthreads();
        if (tid == 0) { __threadfence(); atomicAdd(&g_flag_T[gblk >> 5], 1); }
        return;
    }

    __shared__ float smA[16][17];
    __shared__ float smB[16][132];
    __shared__ float red[256];

    if (bid < 32) {
        // ---- M tile ----
        int e  = bid >> 3;
        int i0 = (bid & 7) * 16;
        int tx = tid & 15, ty = tid >> 4;
        const float* Bm = W2 + (size_t)e * DD * DD;

        float acc[8];
#pragma unroll
        for (int j = 0; j < 8; j++) acc[j] = 0.f;

        int la_i = tid >> 4, la_k = tid & 15;

        for (int kc = 0; kc < DD; kc += 16) {
            __syncthreads();
            smA[la_k][la_i] = W1[(size_t)(i0 + la_i) * DD + kc + la_k];
#pragma unroll
            for (int it = 0; it < 2; it++) {
                int idx = tid + it * 256;
                int br = idx >> 5, bc = idx & 31;
                *(float4*)&smB[br][bc * 4] =
                    *(const float4*)(Bm + (size_t)(kc + br) * DD + bc * 4);
            }
            __syncthreads();
#pragma unroll
            for (int kk = 0; kk < 16; kk++) {
                float a = smA[kk][ty];
                float4 v0 = *(float4*)&smB[kk][tx * 8];
                float4 v1 = *(float4*)&smB[kk][tx * 8 + 4];
                acc[0] += a * v0.x; acc[1] += a * v0.y;
                acc[2] += a * v0.z; acc[3] += a * v0.w;
                acc[4] += a * v1.x; acc[5] += a * v1.y;
                acc[6] += a * v1.z; acc[7] += a * v1.w;
            }
        }
        int row = e * DD + i0 + ty;
        __nv_bfloat162 h0 = __floats2bfloat162_rn(acc[0], acc[1]);
        __nv_bfloat162 h1 = __floats2bfloat162_rn(acc[2], acc[3]);
        __nv_bfloat162 h2 = __floats2bfloat162_rn(acc[4], acc[5]);
        __nv_bfloat162 h3 = __floats2bfloat162_rn(acc[6], acc[7]);
        uint4 pk;
        pk.x = *(unsigned*)&h0; pk.y = *(unsigned*)&h1;
        pk.z = *(unsigned*)&h2; pk.w = *(unsigned*)&h3;
        *(uint4*)(g_Mh + (size_t)row * DD + tx * 8) = pk;
        __syncthreads();
        if (tid == 0) { __threadfence(); atomicAdd(&g_flag_M, 1); }
    } else if (bid == 32) {
        // ---- c ----
        int j = tid & 127, h = tid >> 7;
        float s = (h == 0) ? b2[j] : 0.f;
#pragma unroll 16
        for (int mm = 0; mm < 256; mm++) {
            int m = h * 256 + mm;
            s += b1[m & (DD - 1)] * W2[(size_t)m * DD + j];
        }
        red[tid] = s;
        __syncthreads();
        if (tid < 128) g_c[tid] = red[tid] + red[tid + 128];
        __syncthreads();
        if (tid == 0) { __threadfence(); atomicAdd(&g_flag_M, 1); }
    } else {
        // ---- V (bf16), block v covers rows [64v, 64v+64) == GEMM tile v ----
        int v    = bid - 33;
        int wrp  = v * 8 + (tid >> 5);
        int lane = tid & 31;
#pragma unroll
        for (int i = 0; i < 8; i++) {
            int b  = wrp * 8 + i;
            int en = __ldg(end_node + b);
            int pa = __ldg(path + b);
            float4 ev = *(const float4*)(emb_end  + (size_t)en * DD + lane * 4);
            float4 pv = *(const float4*)(emb_path + (size_t)pa * DD + lane * 4);
            float4 r;
            r.x = ev.x / (1.f + expf(-pv.x));
            r.y = ev.y / (1.f + expf(-pv.y));
            r.z = ev.z / (1.f + expf(-pv.z));
            r.w = ev.w / (1.f + expf(-pv.w));
            __nv_bfloat162 h0 = __floats2bfloat162_rn(r.x, r.y);
            __nv_bfloat162 h1 = __floats2bfloat162_rn(r.z, r.w);
            uint2 pk; pk.x = *(unsigned*)&h0; pk.y = *(unsigned*)&h1;
            *(uint2*)(g_Vh + (size_t)b * DD + lane * 4) = pk;
        }
        __syncthreads();
        if (tid == 0) { __threadfence(); atomicAdd(&g_flag_V[v], 1); }
    }
}

// ---------------------------------------------------------------------------
// Tensor-core GEMM + epilogue, PDL-overlapped. 128 CTAs x 512 threads = 16 warps:
// 4 row-groups (m16) x 2 col-groups (n64) x 2 k-groups (k256). Flag-gated cp.async.
#define B_LD  136
#define A_LD  520
#define V_LD  136
#define BS_ELEMS (AGG_COLS * B_LD)              // 69632 bf16
#define AS_ELEMS (64 * A_LD)                    // 33280 bf16
#define VS_ELEMS (64 * V_LD)                    // 8704  bf16
#define CS_BYTES (DD * 4)                       // 512
#define GEMM_SMEM ((BS_ELEMS + AS_ELEMS + VS_ELEMS) * 2 + CS_BYTES + 64 * 4 * 4)

__global__ __launch_bounds__(512) void k_gemm2(float* __restrict__ out) {
    extern __shared__ char sm_raw[];
    __nv_bfloat16* Bs = (__nv_bfloat16*)sm_raw;
    __nv_bfloat16* As = Bs + BS_ELEMS;
    __nv_bfloat16* Vs = As + AS_ELEMS;
    float*         Cs = (float*)(Vs + VS_ELEMS);
    float (*epi)[4]   = (float (*)[4])(Cs + DD);

    int tid  = threadIdx.x;
    int wid  = tid >> 5;
    int lane = tid & 31;
    int bx   = blockIdx.x;
    int row0 = bx * 64;

    const char* srcB = (const char*)g_Mh;
    const char* srcA = (const char*)(g_aggh + (size_t)row0 * AGG_COLS);
    const char* srcV = (const char*)(g_Vh   + (size_t)row0 * DD);

    // ---- stage M + c once prep done ----
    if (tid == 0) spin_until(&g_flag_M, 33);
    __syncthreads();
#pragma unroll
    for (int it = 0; it < 16; it++) {
        int idx = tid + it * 512;            // 0..8191
        int r = idx >> 4, seg = idx & 15;
        cpasync16(s2u(Bs + r * B_LD + seg * 8), srcB + idx * 16);
    }
    if (tid < 32) cpasync16(s2u((char*)Cs + tid * 16), (const char*)g_c + tid * 16);

    // ---- stage V once its block done ----
    if (tid == 0) spin_until(&g_flag_V[bx], 1);
    __syncthreads();
#pragma unroll
    for (int it = 0; it < 2; it++) {
        int idx = tid + it * 512;            // 0..1023
        int r = idx >> 4, seg = idx & 15;
        cpasync16(s2u(Vs + r * V_LD + seg * 8), srcV + idx * 16);
    }

    // ---- stage A once this tile's 32 gather blocks done ----
    if (tid == 0) spin_until(&g_flag_T[bx], 32);
    __syncthreads();
#pragma unroll
    for (int it = 0; it < 8; it++) {
        int idx = tid + it * 512;            // 0..4095
        int r = idx >> 6, seg = idx & 63;
        cpasync16(s2u(As + r * A_LD + seg * 8), srcA + idx * 16);
    }
    asm volatile("cp.async.commit_group;");
    asm volatile("cp.async.wait_group 0;");
    __syncthreads();

    // ---- warp mapping ----
    int rg = wid & 3;            // row group
    int cg = (wid >> 2) & 1;     // col group
    int kg = wid >> 3;           // k group
    int mrow_base = rg * 16;
    int nbase     = cg * 64;
    int kbase     = kg * 256;

    int li = lane & 7, lq = lane >> 3;
    int a_row = mrow_base + li + ((lq & 1) << 3);
    int a_kof = (lq >> 1) << 3;
    int b_kof = li + ((lq & 1) << 3);
    int b_nof = nbase + ((lq >> 1) << 3);

    float acc[8][4];
#pragma unroll
    for (int f = 0; f < 8; f++)
#pragma unroll
        for (int j = 0; j < 4; j++) acc[f][j] = 0.f;

    unsigned Af[2][4], Bf[2][16];

#define LOADK(buf, kk) {                                                        \
        unsigned aaddr = s2u(As + a_row * A_LD + (kk) + a_kof);                 \
        asm volatile("ldmatrix.sync.aligned.m8n8.x4.shared.b16 {%0,%1,%2,%3}, [%4];" \
                     : "=r"(Af[buf][0]), "=r"(Af[buf][1]),                      \
                       "=r"(Af[buf][2]), "=r"(Af[buf][3]) : "r"(aaddr));        \
        _Pragma("unroll")                                                       \
        for (int f2 = 0; f2 < 4; f2++) {                                        \
            unsigned baddr = s2u(Bs + ((kk) + b_kof) * B_LD + b_nof + f2 * 16); \
            asm volatile("ldmatrix.sync.aligned.m8n8.x4.trans.shared.b16 {%0,%1,%2,%3}, [%4];" \
                         : "=r"(Bf[buf][f2*4+0]), "=r"(Bf[buf][f2*4+1]),        \
                           "=r"(Bf[buf][f2*4+2]), "=r"(Bf[buf][f2*4+3])         \
                         : "r"(baddr));                                         \
        }                                                                       \
    }

    LOADK(0, kbase)
#pragma unroll
    for (int ks = 0; ks < 16; ks++) {
        int cur = ks & 1, nxt = cur ^ 1;
        if (ks < 15) LOADK(nxt, kbase + (ks + 1) * 16)
#pragma unroll
        for (int f2 = 0; f2 < 4; f2++) {
            int f = f2 * 2;
            asm volatile("mma.sync.aligned.m16n8k16.row.col.f32.bf16.bf16.f32 "
                         "{%0,%1,%2,%3}, {%4,%5,%6,%7}, {%8,%9}, {%0,%1,%2,%3};"
                         : "+f"(acc[f][0]), "+f"(acc[f][1]), "+f"(acc[f][2]), "+f"(acc[f][3])
                         : "r"(Af[cur][0]), "r"(Af[cur][1]), "r"(Af[cur][2]), "r"(Af[cur][3]),
                           "r"(Bf[cur][f2*4+0]), "r"(Bf[cur][f2*4+1]));
            asm volatile("mma.sync.aligned.m16n8k16.row.col.f32.bf16.bf16.f32 "
                         "{%0,%1,%2,%3}, {%4,%5,%6,%7}, {%8,%9}, {%0,%1,%2,%3};"
                         : "+f"(acc[f+1][0]), "+f"(acc[f+1][1]), "+f"(acc[f+1][2]), "+f"(acc[f+1][3])
                         : "r"(Af[cur][0]), "r"(Af[cur][1]), "r"(Af[cur][2]), "r"(Af[cur][3]),
                           "r"(Bf[cur][f2*4+2]), "r"(Bf[cur][f2*4+3]));
        }
    }
#undef LOADK

    // ---- fused epilogue: dot with V (smem bf16), reduce, sigmoid ----
    int q = lane & 3, g = lane >> 2;
    int r = mrow_base + g;
    float p0 = 0.f, p1 = 0.f;
#pragma unroll
    for (int f = 0; f < 8; f++) {
        int n = nbase + f * 8 + 2 * q;
        float2 cb = *(const float2*)&Cs[n];
        if (kg) { cb.x = 0.f; cb.y = 0.f; }
        __nv_bfloat162 vh0 = *(const __nv_bfloat162*)(Vs + r * V_LD + n);
        __nv_bfloat162 vh1 = *(const __nv_bfloat162*)(Vs + (r + 8) * V_LD + n);
        float2 v0 = __bfloat1622float2(vh0);
        float2 v1 = __bfloat1622float2(vh1);
        p0 += (acc[f][0] + cb.x) * v0.x + (acc[f][1] + cb.y) * v0.y;
        p1 += (acc[f][2] + cb.x) * v1.x + (acc[f][3] + cb.y) * v1.y;
    }
    p0 += __shfl_xor_sync(0xffffffffu, p0, 1);
    p0 += __shfl_xor_sync(0xffffffffu, p0, 2);
    p1 += __shfl_xor_sync(0xffffffffu, p1, 1);
    p1 += __shfl_xor_sync(0xffffffffu, p1, 2);
    if (q == 0) {
        int s = wid >> 2;                // cg + 2*kg, 0..3
        epi[r][s]     = p0;
        epi[r + 8][s] = p1;
    }
    __syncthreads();
    if (tid < 64) {
        float x = epi[tid][0] + epi[tid][1] + epi[tid][2] + epi[tid][3];
        out[row0 + tid] = 1.f / (1.f + expf(-x));
    }
}

// ---------------------------------------------------------------------------
extern "C" void kernel_launch(void* const* d_in, const int* in_sizes, int n_in,
                              void* d_out, int out_size) {
    const int*   neighbors = (const int*)  d_in[0];
    const int*   end_node  = (const int*)  d_in[1];
    const int*   path      = (const int*)  d_in[2];
    const float* emb_start = (const float*)d_in[3];
    const float* emb_end   = (const float*)d_in[4];
    const float* emb_path  = (const float*)d_in[5];
    const float* W1        = (const float*)d_in[6];
    const float* b1        = (const float*)d_in[7];
    const float* W2        = (const float*)d_in[8];
    const float* b2        = (const float*)d_in[9];
    float*       out       = (float*)d_out;

    cudaFuncSetAttribute(k_gemm2, cudaFuncAttributeMaxDynamicSharedMemorySize,
                         GEMM_SMEM);

    k_reset<<<1, 256>>>();
    k_main<<<PREP_BLKS + GATHER_BLKS, 256>>>(neighbors, emb_start, W1, W2, b1, b2,
                                             end_node, path, emb_end, emb_path);

    cudaLaunchConfig_t cfg = {};
    cfg.gridDim  = dim3(NTILES, 1, 1);
    cfg.blockDim = dim3(512, 1, 1);
    cfg.dynamicSmemBytes = GEMM_SMEM;
    cfg.stream = 0;
    cudaLaunchAttribute attr[1];
    attr[0].id = cudaLaunchAttributeProgrammaticStreamSerialization;
    attr[0].val.programmaticStreamSerializationAllowed = 1;
    cfg.attrs = attr;
    cfg.numAttrs = 1;
    cudaError_t e = cudaLaunchKernelEx(&cfg, k_gemm2, out);
    if (e != cudaSuccess) {
        k_gemm2<<<NTILES, 512, GEMM_SMEM>>>(out);
    }
}